// round 10
// baseline (speedup 1.0000x reference)
#include <cuda_runtime.h>
#include <math.h>

#define GRIDSZ   1024
#define GG       (GRIDSZ * GRIDSZ)
#define NAGENTS  262144
#define NCH      8
#define NHID     64
#define DT       0.1f
#define SENS_ANG 0.6f
#define SENS_LEN 3.0f
#define DECAY    0.99f

// Scratch (static __device__ arrays: allocation-free per harness rules)
__device__ float g_latT[GG * NCH];          // lattice transposed to (x,y,c), 32 MB
__device__ float g_dpher[NAGENTS * NCH];    // per-agent d_pheromone, 8 MB
__device__ int   g_winner[GG];              // 0 = none, else agent_id+1 (zero-init, reset by latout)

// ---------------------------------------------------------------------------
// packed fp32x2 helpers (FFMA2 — only reachable via PTX fma.rn.f32x2)
// ---------------------------------------------------------------------------
typedef unsigned long long u64t;

__device__ __forceinline__ u64t pk2(float lo, float hi) {
    u64t r; asm("mov.b64 %0, {%1, %2};" : "=l"(r) : "f"(lo), "f"(hi)); return r;
}
__device__ __forceinline__ void upk2(u64t v, float& lo, float& hi) {
    asm("mov.b64 {%0, %1}, %2;" : "=f"(lo), "=f"(hi) : "l"(v));
}
__device__ __forceinline__ u64t fma2(u64t a, u64t b, u64t c) {
    u64t d; asm("fma.rn.f32x2 %0, %1, %2, %3;" : "=l"(d) : "l"(a), "l"(b), "l"(c)); return d;
}
__device__ __forceinline__ u64t packbits(float lo, float hi) {
    return ((u64t)__float_as_uint(hi) << 32) | (u64t)__float_as_uint(lo);
}

// fast tanh: 1 - 2/(exp(2a)+1); exact saturation, ~1e-7 rel error
__device__ __forceinline__ float fast_tanh(float a) {
    float t = __expf(2.0f * a);
    return 1.0f - __fdividef(2.0f, t + 1.0f);
}

// ---------------------------------------------------------------------------
// Kernel 1: transpose lattice (C,G,G) -> (G,G,C). 4 cells per thread:
// 8x LDG.128 reads, 8x STG.128 writes (128B contiguous per thread).
// ---------------------------------------------------------------------------
__global__ void __launch_bounds__(256) transpose_k(const float* __restrict__ lat) {
    int t = blockIdx.x * blockDim.x + threadIdx.x;   // cell-group id
    int base = t * 4;                                 // first cell (x*G+y)
    float4 c[NCH];
    #pragma unroll
    for (int ch = 0; ch < NCH; ch++)
        c[ch] = *reinterpret_cast<const float4*>(&lat[(size_t)ch * GG + base]);
    float4* dst = reinterpret_cast<float4*>(&g_latT[(size_t)base * NCH]);
    #pragma unroll
    for (int k = 0; k < 4; k++) {
        float e[NCH];
        #pragma unroll
        for (int ch = 0; ch < NCH; ch++)
            e[ch] = (k == 0) ? c[ch].x : (k == 1) ? c[ch].y : (k == 2) ? c[ch].z : c[ch].w;
        dst[2 * k + 0] = make_float4(e[0], e[1], e[2], e[3]);
        dst[2 * k + 1] = make_float4(e[4], e[5], e[6], e[7]);
    }
}

// ---------------------------------------------------------------------------
// Kernel 2: per-agent sense + MLP (packed f32x2) + outputs + scatter staging
// ---------------------------------------------------------------------------
__global__ void __launch_bounds__(256) agent_k(
    const float* __restrict__ pos, const float* __restrict__ vel,
    const float* __restrict__ W1, const float* __restrict__ b1,
    const float* __restrict__ W2, const float* __restrict__ b2,
    float* __restrict__ out)
{
    // W1 packed for hidden-pair jp: sW1p[jp*12+q] = { (W1[2q][2jp],W1[2q][2jp+1]),
    //                                                 (W1[2q+1][2jp],W1[2q+1][2jp+1]) }
    __shared__ ulonglong2 sW1p[32 * 12];
    // W2 rows padded to 12: sW2p[j*3+q] = { (W2[j][4q],W2[j][4q+1]), (W2[j][4q+2],W2[j][4q+3]) }
    __shared__ ulonglong2 sW2p[NHID * 3];
    __shared__ float2 sb1[32];
    __shared__ float  sb2[12];

    int tid = threadIdx.x;
    for (int t = tid; t < 32 * 12; t += blockDim.x) {
        int jp = t / 12, q = t % 12;
        int i0 = 2 * q, i1 = 2 * q + 1;
        float a0 = W1[i0 * NHID + 2 * jp], a1 = W1[i0 * NHID + 2 * jp + 1];
        float c0 = W1[i1 * NHID + 2 * jp], c1 = W1[i1 * NHID + 2 * jp + 1];
        sW1p[t] = make_ulonglong2(packbits(a0, a1), packbits(c0, c1));
    }
    for (int t = tid; t < NHID * 3; t += blockDim.x) {
        int j = t / 3, q = t % 3;
        float e[4];
        #pragma unroll
        for (int u = 0; u < 4; u++) {
            int k = 4 * q + u;
            e[u] = (k < 10) ? W2[j * 10 + k] : 0.0f;
        }
        sW2p[t] = make_ulonglong2(packbits(e[0], e[1]), packbits(e[2], e[3]));
    }
    if (tid < 32) sb1[tid] = make_float2(b1[2 * tid], b1[2 * tid + 1]);
    if (tid < 12) sb2[tid] = (tid < 10) ? b2[tid] : 0.0f;
    __syncthreads();

    int i = blockIdx.x * blockDim.x + tid;

    float px = pos[i], py = pos[NAGENTS + i];
    float vx = vel[i], vy = vel[NAGENTS + i];

    float theta = atan2f(vy, vx);
    const float offs[3] = {0.0f, SENS_ANG, -SENS_ANG};

    // ---- sense: 3 sensors x 3x3 window, channel-innermost lattice ----
    u64t f2[24];   // feature i duplicated into both f32x2 lanes
    #pragma unroll
    for (int s = 0; s < 3; s++) {
        float sn, cs;
        sincosf(theta + offs[s], &sn, &cs);
        // match JAX mul-then-add rounding (no fma contraction before rint)
        int cx = (int)rintf(__fadd_rn(px, __fmul_rn(SENS_LEN, cs)));
        int cy = (int)rintf(__fadd_rn(py, __fmul_rn(SENS_LEN, sn)));

        float acc[NCH];
        #pragma unroll
        for (int c = 0; c < NCH; c++) acc[c] = 0.0f;

        #pragma unroll
        for (int dx = -1; dx <= 1; dx++) {
            int x = (cx + dx + 2 * GRIDSZ) & (GRIDSZ - 1);
            #pragma unroll
            for (int dy = -1; dy <= 1; dy++) {
                int y = (cy + dy + 2 * GRIDSZ) & (GRIDSZ - 1);
                const float4* p = reinterpret_cast<const float4*>(
                    &g_latT[((size_t)x * GRIDSZ + y) * NCH]);
                float4 v0 = p[0], v1 = p[1];
                acc[0] += v0.x; acc[1] += v0.y; acc[2] += v0.z; acc[3] += v0.w;
                acc[4] += v1.x; acc[5] += v1.y; acc[6] += v1.z; acc[7] += v1.w;
            }
        }
        #pragma unroll
        for (int c = 0; c < NCH; c++) f2[s * NCH + c] = pk2(acc[c], acc[c]);
    }

    // ---- MLP, all math as packed f32x2 (identical IEEE fp32 per lane) ----
    u64t o2[6];
    #pragma unroll
    for (int kk = 0; kk < 6; kk++) o2[kk] = pk2(sb2[2 * kk], sb2[2 * kk + 1]);

    #pragma unroll 2
    for (int jp = 0; jp < 32; jp++) {
        float2 bb = sb1[jp];
        u64t acc = pk2(bb.x, bb.y);
        const ulonglong2* w1r = &sW1p[jp * 12];
        #pragma unroll
        for (int q = 0; q < 12; q++) {
            ulonglong2 wv = w1r[q];
            acc = fma2(f2[2 * q],     wv.x, acc);
            acc = fma2(f2[2 * q + 1], wv.y, acc);
        }
        float a0, a1; upk2(acc, a0, a1);
        u64t h0d = pk2(fast_tanh(a0), fast_tanh(a0));
        u64t h1d = pk2(fast_tanh(a1), fast_tanh(a1));

        const ulonglong2* w2a = &sW2p[(2 * jp) * 3];
        const ulonglong2* w2b = &sW2p[(2 * jp + 1) * 3];
        #pragma unroll
        for (int q = 0; q < 3; q++) {
            ulonglong2 wa = w2a[q];
            o2[2 * q]     = fma2(h0d, wa.x, o2[2 * q]);
            o2[2 * q + 1] = fma2(h0d, wa.y, o2[2 * q + 1]);
        }
        #pragma unroll
        for (int q = 0; q < 3; q++) {
            ulonglong2 wb = w2b[q];
            o2[2 * q]     = fma2(h1d, wb.x, o2[2 * q]);
            o2[2 * q + 1] = fma2(h1d, wb.y, o2[2 * q + 1]);
        }
    }

    float o[12];
    #pragma unroll
    for (int kk = 0; kk < 6; kk++) upk2(o2[kk], o[2 * kk], o[2 * kk + 1]);

    // new_pos = (pos + new_vel*DT) mod GRID (python floor-mod, b>0)
    float nx = fmodf(px + o[0] * DT, (float)GRIDSZ); if (nx < 0.0f) nx += (float)GRIDSZ;
    float ny = fmodf(py + o[1] * DT, (float)GRIDSZ); if (ny < 0.0f) ny += (float)GRIDSZ;

    out[0 * NAGENTS + i] = nx;
    out[1 * NAGENTS + i] = ny;
    out[2 * NAGENTS + i] = o[0];
    out[3 * NAGENTS + i] = o[1];

    // stage d_pheromone (channels 2..9) for the scatter pass
    float4* dp = reinterpret_cast<float4*>(&g_dpher[(size_t)i * NCH]);
    dp[0] = make_float4(o[2], o[3], o[4], o[5]);
    dp[1] = make_float4(o[6], o[7], o[8], o[9]);

    // deterministic duplicate resolution: max agent index wins (== last-wins
    // under sequential scatter). atomicMax is order-independent -> replayable.
    int pxi = (int)rintf(px);
    int pyi = (int)rintf(py);
    atomicMax(&g_winner[pxi * GRIDSZ + pyi], i + 1);
}

// ---------------------------------------------------------------------------
// Kernel 3: fused decay + scatter + winner reset. 4 cells per thread, float4
// per channel plane.
// ---------------------------------------------------------------------------
__global__ void __launch_bounds__(256) latout_k(const float* __restrict__ lat,
                                               float* __restrict__ out) {
    int t = blockIdx.x * blockDim.x + threadIdx.x;
    int base = t * 4;

    int4 w4 = *reinterpret_cast<const int4*>(&g_winner[base]);
    int wk[4] = {w4.x, w4.y, w4.z, w4.w};
    bool any = (w4.x | w4.y | w4.z | w4.w) != 0;
    if (any)
        *reinterpret_cast<int4*>(&g_winner[base]) = make_int4(0, 0, 0, 0);

    float up[4][NCH];
    #pragma unroll
    for (int k = 0; k < 4; k++) {
        if (wk[k]) {
            const float4* dp = reinterpret_cast<const float4*>(
                &g_dpher[(size_t)(wk[k] - 1) * NCH]);
            float4 a = dp[0], b = dp[1];
            up[k][0] = a.x; up[k][1] = a.y; up[k][2] = a.z; up[k][3] = a.w;
            up[k][4] = b.x; up[k][5] = b.y; up[k][6] = b.z; up[k][7] = b.w;
        }
    }

    float* olat = out + 4 * NAGENTS;
    #pragma unroll
    for (int c = 0; c < NCH; c++) {
        float4 v = *reinterpret_cast<const float4*>(&lat[(size_t)c * GG + base]);
        if (any) {
            if (wk[0]) v.x = fmaxf(v.x + DT * up[0][c], 0.0f);
            if (wk[1]) v.y = fmaxf(v.y + DT * up[1][c], 0.0f);
            if (wk[2]) v.z = fmaxf(v.z + DT * up[2][c], 0.0f);
            if (wk[3]) v.w = fmaxf(v.w + DT * up[3][c], 0.0f);
        }
        v.x *= DECAY; v.y *= DECAY; v.z *= DECAY; v.w *= DECAY;
        *reinterpret_cast<float4*>(&olat[(size_t)c * GG + base]) = v;
    }
}

// ---------------------------------------------------------------------------
extern "C" void kernel_launch(void* const* d_in, const int* in_sizes, int n_in,
                              void* d_out, int out_size) {
    const float* agent_pos = (const float*)d_in[0];   // (2, N)
    const float* agent_vel = (const float*)d_in[1];   // (2, N)
    const float* lattice   = (const float*)d_in[2];   // (8, 1024, 1024)
    const float* W1        = (const float*)d_in[3];   // (24, 64)
    const float* b1        = (const float*)d_in[4];   // (64,)
    const float* W2        = (const float*)d_in[5];   // (64, 10)
    const float* b2        = (const float*)d_in[6];   // (10,)
    float* out = (float*)d_out;

    transpose_k<<<GG / 4 / 256, 256>>>(lattice);
    agent_k<<<NAGENTS / 256, 256>>>(agent_pos, agent_vel, W1, b1, W2, b2, out);
    latout_k<<<GG / 4 / 256, 256>>>(lattice, out);
}

// round 11
// speedup vs baseline: 1.5537x; 1.5537x over previous
#include <cuda_runtime.h>
#include <math.h>

#define GRIDSZ   1024
#define GG       (GRIDSZ * GRIDSZ)
#define NAGENTS  262144
#define NCH      8
#define NHID     64
#define DT       0.1f
#define SENS_ANG 0.6f
#define SENS_LEN 3.0f
#define DECAY    0.99f

// Scratch (static __device__ arrays: allocation-free per harness rules)
__device__ float g_latT[GG * NCH];          // lattice transposed to (x,y,c), 32 MB
__device__ float g_dpher[NAGENTS * NCH];    // per-agent d_pheromone, 8 MB
__device__ int   g_winner[GG];              // 0 = none, else agent_id+1 (zero-init, reset by latout)

// ---------------------------------------------------------------------------
// packed fp32x2 helpers (FFMA2 — only reachable via PTX fma.rn.f32x2)
// ---------------------------------------------------------------------------
typedef unsigned long long u64t;

__device__ __forceinline__ u64t pk2(float lo, float hi) {
    u64t r; asm("mov.b64 %0, {%1, %2};" : "=l"(r) : "f"(lo), "f"(hi)); return r;
}
__device__ __forceinline__ void upk2(u64t v, float& lo, float& hi) {
    asm("mov.b64 {%0, %1}, %2;" : "=f"(lo), "=f"(hi) : "l"(v));
}
__device__ __forceinline__ u64t fma2(u64t a, u64t b, u64t c) {
    u64t d; asm("fma.rn.f32x2 %0, %1, %2, %3;" : "=l"(d) : "l"(a), "l"(b), "l"(c)); return d;
}
__device__ __forceinline__ u64t packbits(float lo, float hi) {
    return ((u64t)__float_as_uint(hi) << 32) | (u64t)__float_as_uint(lo);
}

// fast tanh: 1 - 2/(exp(2a)+1); exact saturation, ~1e-7 rel error
__device__ __forceinline__ float fast_tanh(float a) {
    float t = __expf(2.0f * a);
    return 1.0f - __fdividef(2.0f, t + 1.0f);
}

// ---------------------------------------------------------------------------
// Kernel 1: transpose lattice (C,G,G) -> (G,G,C). R1 form: 1 cell/thread,
// maximum thread-level parallelism (this kernel is latency-bound; the R10
// 4-cells/thread variant cut MLP 4x and regressed 14.3 -> 22.5 us).
// ---------------------------------------------------------------------------
__global__ void __launch_bounds__(256) transpose_k(const float* __restrict__ lat) {
    int idx = blockIdx.x * blockDim.x + threadIdx.x;   // x*GRIDSZ + y
    if (idx >= GG) return;
    float4 a, b;
    a.x = lat[0 * GG + idx];
    a.y = lat[1 * GG + idx];
    a.z = lat[2 * GG + idx];
    a.w = lat[3 * GG + idx];
    b.x = lat[4 * GG + idx];
    b.y = lat[5 * GG + idx];
    b.z = lat[6 * GG + idx];
    b.w = lat[7 * GG + idx];
    float4* dst = reinterpret_cast<float4*>(&g_latT[(size_t)idx * NCH]);
    dst[0] = a;
    dst[1] = b;
}

// ---------------------------------------------------------------------------
// Kernel 2: per-agent sense + MLP + outputs + scatter staging.
// Register-lean FFMA2: layer 1 pairs along the FEATURE axis (features packed
// once as 12 u64 = 24 regs, same cost as scalar), layer 2 pairs along the
// OUTPUT axis (h duplicated transiently). No f2[24]-style register doubling.
// ---------------------------------------------------------------------------
__global__ void __launch_bounds__(256) agent_k(
    const float* __restrict__ pos, const float* __restrict__ vel,
    const float* __restrict__ W1, const float* __restrict__ b1,
    const float* __restrict__ W2, const float* __restrict__ b2,
    float* __restrict__ out)
{
    // sW1p[j*6+q] = { (W1[4q][j], W1[4q+1][j]), (W1[4q+2][j], W1[4q+3][j]) }
    __shared__ ulonglong2 sW1p[NHID * 6];
    // sW2p[j*3+q] = { (W2[j][4q], W2[j][4q+1]), (W2[j][4q+2], W2[j][4q+3]) }, k>=10 -> 0
    __shared__ ulonglong2 sW2p[NHID * 3];
    __shared__ float sb1[NHID];
    __shared__ float sb2[12];

    int tid = threadIdx.x;
    for (int t = tid; t < NHID * 6; t += blockDim.x) {
        int j = t / 6, q = t % 6;
        float e0 = W1[(4 * q + 0) * NHID + j];
        float e1 = W1[(4 * q + 1) * NHID + j];
        float e2 = W1[(4 * q + 2) * NHID + j];
        float e3 = W1[(4 * q + 3) * NHID + j];
        sW1p[t] = make_ulonglong2(packbits(e0, e1), packbits(e2, e3));
    }
    for (int t = tid; t < NHID * 3; t += blockDim.x) {
        int j = t / 3, q = t % 3;
        float e[4];
        #pragma unroll
        for (int u = 0; u < 4; u++) {
            int k = 4 * q + u;
            e[u] = (k < 10) ? W2[j * 10 + k] : 0.0f;
        }
        sW2p[t] = make_ulonglong2(packbits(e[0], e[1]), packbits(e[2], e[3]));
    }
    if (tid < NHID) sb1[tid] = b1[tid];
    if (tid < 12)   sb2[tid] = (tid < 10) ? b2[tid] : 0.0f;
    __syncthreads();

    int i = blockIdx.x * blockDim.x + tid;

    float px = pos[i], py = pos[NAGENTS + i];
    float vx = vel[i], vy = vel[NAGENTS + i];

    float theta = atan2f(vy, vx);
    const float offs[3] = {0.0f, SENS_ANG, -SENS_ANG};

    // ---- sense: 3 sensors x 3x3 window, channel-innermost lattice ----
    // features packed as pairs: f2[p] = (feat[2p], feat[2p+1]); 12 u64 = 24 regs
    u64t f2[12];
    #pragma unroll
    for (int s = 0; s < 3; s++) {
        float sn, cs;
        sincosf(theta + offs[s], &sn, &cs);
        // match JAX mul-then-add rounding (no fma contraction before rint)
        int cx = (int)rintf(__fadd_rn(px, __fmul_rn(SENS_LEN, cs)));
        int cy = (int)rintf(__fadd_rn(py, __fmul_rn(SENS_LEN, sn)));

        float acc[NCH];
        #pragma unroll
        for (int c = 0; c < NCH; c++) acc[c] = 0.0f;

        #pragma unroll
        for (int dx = -1; dx <= 1; dx++) {
            int x = (cx + dx + 2 * GRIDSZ) & (GRIDSZ - 1);
            #pragma unroll
            for (int dy = -1; dy <= 1; dy++) {
                int y = (cy + dy + 2 * GRIDSZ) & (GRIDSZ - 1);
                const float4* p = reinterpret_cast<const float4*>(
                    &g_latT[((size_t)x * GRIDSZ + y) * NCH]);
                float4 v0 = p[0], v1 = p[1];
                acc[0] += v0.x; acc[1] += v0.y; acc[2] += v0.z; acc[3] += v0.w;
                acc[4] += v1.x; acc[5] += v1.y; acc[6] += v1.z; acc[7] += v1.w;
            }
        }
        #pragma unroll
        for (int c = 0; c < 4; c++)
            f2[s * 4 + c] = pk2(acc[2 * c], acc[2 * c + 1]);
    }

    // ---- MLP ----
    // layer 1 per hidden j: acc2 accumulates even/odd feature products in two
    // lanes (12 FFMA2), then lane-sum + bias -> tanh.
    // layer 2: h duplicated, outputs paired (6 FFMA2).
    u64t o2[6];
    #pragma unroll
    for (int kk = 0; kk < 6; kk++) o2[kk] = pk2(sb2[2 * kk], sb2[2 * kk + 1]);

    #pragma unroll 4
    for (int j = 0; j < NHID; j++) {
        u64t acc = pk2(sb1[j], 0.0f);
        const ulonglong2* w1r = &sW1p[j * 6];
        #pragma unroll
        for (int q = 0; q < 6; q++) {
            ulonglong2 w = w1r[q];
            acc = fma2(f2[2 * q],     w.x, acc);
            acc = fma2(f2[2 * q + 1], w.y, acc);
        }
        float lo, hi; upk2(acc, lo, hi);
        float h = fast_tanh(lo + hi);
        u64t hd = pk2(h, h);

        const ulonglong2* w2r = &sW2p[j * 3];
        #pragma unroll
        for (int q = 0; q < 3; q++) {
            ulonglong2 w = w2r[q];
            o2[2 * q]     = fma2(hd, w.x, o2[2 * q]);
            o2[2 * q + 1] = fma2(hd, w.y, o2[2 * q + 1]);
        }
    }

    float o[12];
    #pragma unroll
    for (int kk = 0; kk < 6; kk++) upk2(o2[kk], o[2 * kk], o[2 * kk + 1]);

    // new_pos = (pos + new_vel*DT) mod GRID (python floor-mod, b>0)
    float nx = fmodf(px + o[0] * DT, (float)GRIDSZ); if (nx < 0.0f) nx += (float)GRIDSZ;
    float ny = fmodf(py + o[1] * DT, (float)GRIDSZ); if (ny < 0.0f) ny += (float)GRIDSZ;

    out[0 * NAGENTS + i] = nx;
    out[1 * NAGENTS + i] = ny;
    out[2 * NAGENTS + i] = o[0];
    out[3 * NAGENTS + i] = o[1];

    // stage d_pheromone (channels 2..9) for the scatter pass
    float4* dp = reinterpret_cast<float4*>(&g_dpher[(size_t)i * NCH]);
    dp[0] = make_float4(o[2], o[3], o[4], o[5]);
    dp[1] = make_float4(o[6], o[7], o[8], o[9]);

    // deterministic duplicate resolution: max agent index wins (== last-wins
    // under sequential scatter). atomicMax is order-independent -> replayable.
    int pxi = (int)rintf(px);
    int pyi = (int)rintf(py);
    atomicMax(&g_winner[pxi * GRIDSZ + pyi], i + 1);
}

// ---------------------------------------------------------------------------
// Kernel 3: fused decay + scatter + winner reset. R1 form: 1 cell/thread
// (latency-bound streaming pass; keep max parallelism).
// ---------------------------------------------------------------------------
__global__ void __launch_bounds__(256) latout_k(const float* __restrict__ lat,
                                               float* __restrict__ out) {
    int idx = blockIdx.x * blockDim.x + threadIdx.x;   // x*GRIDSZ + y
    if (idx >= GG) return;
    int w = g_winner[idx];
    float up[NCH];
    if (w) {
        g_winner[idx] = 0;   // reset for next graph replay
        const float4* dp = reinterpret_cast<const float4*>(&g_dpher[(size_t)(w - 1) * NCH]);
        float4 a = dp[0], b = dp[1];
        up[0] = a.x; up[1] = a.y; up[2] = a.z; up[3] = a.w;
        up[4] = b.x; up[5] = b.y; up[6] = b.z; up[7] = b.w;
    }
    float* olat = out + 4 * NAGENTS;   // lattice section of output
    #pragma unroll
    for (int c = 0; c < NCH; c++) {
        float v = lat[(size_t)c * GG + idx];
        if (w) v = fmaxf(v + DT * up[c], 0.0f);
        olat[(size_t)c * GG + idx] = v * DECAY;
    }
}

// ---------------------------------------------------------------------------
extern "C" void kernel_launch(void* const* d_in, const int* in_sizes, int n_in,
                              void* d_out, int out_size) {
    const float* agent_pos = (const float*)d_in[0];   // (2, N)
    const float* agent_vel = (const float*)d_in[1];   // (2, N)
    const float* lattice   = (const float*)d_in[2];   // (8, 1024, 1024)
    const float* W1        = (const float*)d_in[3];   // (24, 64)
    const float* b1        = (const float*)d_in[4];   // (64,)
    const float* W2        = (const float*)d_in[5];   // (64, 10)
    const float* b2        = (const float*)d_in[6];   // (10,)
    float* out = (float*)d_out;

    transpose_k<<<(GG + 255) / 256, 256>>>(lattice);
    agent_k<<<NAGENTS / 256, 256>>>(agent_pos, agent_vel, W1, b1, W2, b2, out);
    latout_k<<<(GG + 255) / 256, 256>>>(lattice, out);
}

// round 12
// speedup vs baseline: 1.5897x; 1.0232x over previous
#include <cuda_runtime.h>
#include <math.h>

#define GRIDSZ   1024
#define GG       (GRIDSZ * GRIDSZ)
#define NAGENTS  262144
#define NHALF    (NAGENTS / 2)
#define NCH      8
#define NHID     64
#define DT       0.1f
#define SENS_ANG 0.6f
#define SENS_LEN 3.0f
#define DECAY    0.99f

// Scratch (static __device__ arrays: allocation-free per harness rules)
__device__ float g_latT[GG * NCH];          // lattice transposed to (x,y,c), 32 MB
__device__ float g_dpher[NAGENTS * NCH];    // per-agent d_pheromone, 8 MB
__device__ int   g_winner[GG];              // 0 = none, else agent_id+1 (zero-init, reset by latout)

// ---------------------------------------------------------------------------
// packed fp32x2 helpers (FFMA2 — only reachable via PTX fma.rn.f32x2)
// ---------------------------------------------------------------------------
typedef unsigned long long u64t;

__device__ __forceinline__ u64t pk2(float lo, float hi) {
    u64t r; asm("mov.b64 %0, {%1, %2};" : "=l"(r) : "f"(lo), "f"(hi)); return r;
}
__device__ __forceinline__ void upk2(u64t v, float& lo, float& hi) {
    asm("mov.b64 {%0, %1}, %2;" : "=f"(lo), "=f"(hi) : "l"(v));
}
__device__ __forceinline__ u64t fma2(u64t a, u64t b, u64t c) {
    u64t d; asm("fma.rn.f32x2 %0, %1, %2, %3;" : "=l"(d) : "l"(a), "l"(b), "l"(c)); return d;
}
__device__ __forceinline__ u64t packbits(float lo, float hi) {
    return ((u64t)__float_as_uint(hi) << 32) | (u64t)__float_as_uint(lo);
}

// fast tanh: 1 - 2/(exp(2a)+1); exact saturation, ~1e-7 rel error
__device__ __forceinline__ float fast_tanh(float a) {
    float t = __expf(2.0f * a);
    return 1.0f - __fdividef(2.0f, t + 1.0f);
}

// ---------------------------------------------------------------------------
// Kernel 1: transpose lattice (C,G,G) -> (G,G,C). 1 cell/thread (latency-
// bound: R10 showed 4 cells/thread cuts MLP 4x and regresses 14.3 -> 22.5us).
// ---------------------------------------------------------------------------
__global__ void __launch_bounds__(256) transpose_k(const float* __restrict__ lat) {
    int idx = blockIdx.x * blockDim.x + threadIdx.x;   // x*GRIDSZ + y
    if (idx >= GG) return;
    float4 a, b;
    a.x = lat[0 * GG + idx];
    a.y = lat[1 * GG + idx];
    a.z = lat[2 * GG + idx];
    a.w = lat[3 * GG + idx];
    b.x = lat[4 * GG + idx];
    b.y = lat[5 * GG + idx];
    b.z = lat[6 * GG + idx];
    b.w = lat[7 * GG + idx];
    float4* dst = reinterpret_cast<float4*>(&g_latT[(size_t)idx * NCH]);
    dst[0] = a;
    dst[1] = b;
}

// ---------------------------------------------------------------------------
// Kernel 2: sense + MLP + outputs, TWO agents per thread (i and i+NHALF).
// Weight LDS amortized over both agents; two independent FMA chains per j
// give ILP to hide LDS/FFMA latency at reduced occupancy.
// ---------------------------------------------------------------------------
__global__ void __launch_bounds__(256) agent_k(
    const float* __restrict__ pos, const float* __restrict__ vel,
    const float* __restrict__ W1, const float* __restrict__ b1,
    const float* __restrict__ W2, const float* __restrict__ b2,
    float* __restrict__ out)
{
    // sW1p[j*6+q] = { (W1[4q][j], W1[4q+1][j]), (W1[4q+2][j], W1[4q+3][j]) }
    __shared__ ulonglong2 sW1p[NHID * 6];
    // sW2p[j*3+q] = { (W2[j][4q], W2[j][4q+1]), (W2[j][4q+2], W2[j][4q+3]) }, k>=10 -> 0
    __shared__ ulonglong2 sW2p[NHID * 3];
    __shared__ float sb1[NHID];
    __shared__ float sb2[12];

    int tid = threadIdx.x;
    for (int t = tid; t < NHID * 6; t += blockDim.x) {
        int j = t / 6, q = t % 6;
        float e0 = W1[(4 * q + 0) * NHID + j];
        float e1 = W1[(4 * q + 1) * NHID + j];
        float e2 = W1[(4 * q + 2) * NHID + j];
        float e3 = W1[(4 * q + 3) * NHID + j];
        sW1p[t] = make_ulonglong2(packbits(e0, e1), packbits(e2, e3));
    }
    for (int t = tid; t < NHID * 3; t += blockDim.x) {
        int j = t / 3, q = t % 3;
        float e[4];
        #pragma unroll
        for (int u = 0; u < 4; u++) {
            int k = 4 * q + u;
            e[u] = (k < 10) ? W2[j * 10 + k] : 0.0f;
        }
        sW2p[t] = make_ulonglong2(packbits(e[0], e[1]), packbits(e[2], e[3]));
    }
    if (tid < NHID) sb1[tid] = b1[tid];
    if (tid < 12)   sb2[tid] = (tid < 10) ? b2[tid] : 0.0f;
    __syncthreads();

    int t0 = blockIdx.x * blockDim.x + tid;

    float px[2], py[2];
    u64t  f2[2][12];

    // ---- sense both agents ----
    #pragma unroll
    for (int a = 0; a < 2; a++) {
        int i = t0 + a * NHALF;
        float pxa = pos[i], pya = pos[NAGENTS + i];
        float vxa = vel[i], vya = vel[NAGENTS + i];
        px[a] = pxa; py[a] = pya;

        float theta = atan2f(vya, vxa);
        const float offs[3] = {0.0f, SENS_ANG, -SENS_ANG};

        #pragma unroll
        for (int s = 0; s < 3; s++) {
            float sn, cs;
            sincosf(theta + offs[s], &sn, &cs);
            // match JAX mul-then-add rounding (no fma contraction before rint)
            int cx = (int)rintf(__fadd_rn(pxa, __fmul_rn(SENS_LEN, cs)));
            int cy = (int)rintf(__fadd_rn(pya, __fmul_rn(SENS_LEN, sn)));

            float acc[NCH];
            #pragma unroll
            for (int c = 0; c < NCH; c++) acc[c] = 0.0f;

            #pragma unroll
            for (int dx = -1; dx <= 1; dx++) {
                int x = (cx + dx + 2 * GRIDSZ) & (GRIDSZ - 1);
                #pragma unroll
                for (int dy = -1; dy <= 1; dy++) {
                    int y = (cy + dy + 2 * GRIDSZ) & (GRIDSZ - 1);
                    const float4* p = reinterpret_cast<const float4*>(
                        &g_latT[((size_t)x * GRIDSZ + y) * NCH]);
                    float4 v0 = p[0], v1 = p[1];
                    acc[0] += v0.x; acc[1] += v0.y; acc[2] += v0.z; acc[3] += v0.w;
                    acc[4] += v1.x; acc[5] += v1.y; acc[6] += v1.z; acc[7] += v1.w;
                }
            }
            #pragma unroll
            for (int c = 0; c < 4; c++)
                f2[a][s * 4 + c] = pk2(acc[2 * c], acc[2 * c + 1]);
        }
    }

    // ---- MLP: shared weight loads, two independent accumulator chains ----
    u64t o2[2][6];
    #pragma unroll
    for (int kk = 0; kk < 6; kk++) {
        u64t b = pk2(sb2[2 * kk], sb2[2 * kk + 1]);
        o2[0][kk] = b; o2[1][kk] = b;
    }

    #pragma unroll 2
    for (int j = 0; j < NHID; j++) {
        float bj = sb1[j];
        u64t acc0 = pk2(bj, 0.0f);
        u64t acc1 = acc0;
        const ulonglong2* w1r = &sW1p[j * 6];
        #pragma unroll
        for (int q = 0; q < 6; q++) {
            ulonglong2 w = w1r[q];
            acc0 = fma2(f2[0][2 * q],     w.x, acc0);
            acc1 = fma2(f2[1][2 * q],     w.x, acc1);
            acc0 = fma2(f2[0][2 * q + 1], w.y, acc0);
            acc1 = fma2(f2[1][2 * q + 1], w.y, acc1);
        }
        float lo0, hi0, lo1, hi1;
        upk2(acc0, lo0, hi0);
        upk2(acc1, lo1, hi1);
        float h0 = fast_tanh(lo0 + hi0);
        float h1 = fast_tanh(lo1 + hi1);
        u64t hd0 = pk2(h0, h0);
        u64t hd1 = pk2(h1, h1);

        const ulonglong2* w2r = &sW2p[j * 3];
        #pragma unroll
        for (int q = 0; q < 3; q++) {
            ulonglong2 w = w2r[q];
            o2[0][2 * q]     = fma2(hd0, w.x, o2[0][2 * q]);
            o2[1][2 * q]     = fma2(hd1, w.x, o2[1][2 * q]);
            o2[0][2 * q + 1] = fma2(hd0, w.y, o2[0][2 * q + 1]);
            o2[1][2 * q + 1] = fma2(hd1, w.y, o2[1][2 * q + 1]);
        }
    }

    // ---- outputs for both agents ----
    #pragma unroll
    for (int a = 0; a < 2; a++) {
        int i = t0 + a * NHALF;
        float o[12];
        #pragma unroll
        for (int kk = 0; kk < 6; kk++) upk2(o2[a][kk], o[2 * kk], o[2 * kk + 1]);

        // new_pos = (pos + new_vel*DT) mod GRID (python floor-mod, b>0)
        float nx = fmodf(px[a] + o[0] * DT, (float)GRIDSZ); if (nx < 0.0f) nx += (float)GRIDSZ;
        float ny = fmodf(py[a] + o[1] * DT, (float)GRIDSZ); if (ny < 0.0f) ny += (float)GRIDSZ;

        out[0 * NAGENTS + i] = nx;
        out[1 * NAGENTS + i] = ny;
        out[2 * NAGENTS + i] = o[0];
        out[3 * NAGENTS + i] = o[1];

        float4* dp = reinterpret_cast<float4*>(&g_dpher[(size_t)i * NCH]);
        dp[0] = make_float4(o[2], o[3], o[4], o[5]);
        dp[1] = make_float4(o[6], o[7], o[8], o[9]);

        // deterministic duplicate resolution: max agent index wins (== last-
        // wins under sequential scatter). atomicMax is order-independent.
        int pxi = (int)rintf(px[a]);
        int pyi = (int)rintf(py[a]);
        atomicMax(&g_winner[pxi * GRIDSZ + pyi], i + 1);
    }
}

// ---------------------------------------------------------------------------
// Kernel 3: fused decay + scatter + winner reset. Reads lattice values from
// g_latT (same floats, L2-resident, 32B-contiguous per thread) instead of
// re-reading the original planes from DRAM.
// ---------------------------------------------------------------------------
__global__ void __launch_bounds__(256) latout_k(float* __restrict__ out) {
    int idx = blockIdx.x * blockDim.x + threadIdx.x;   // x*GRIDSZ + y
    if (idx >= GG) return;
    int w = g_winner[idx];
    float up[NCH];
    if (w) {
        g_winner[idx] = 0;   // reset for next graph replay
        const float4* dp = reinterpret_cast<const float4*>(&g_dpher[(size_t)(w - 1) * NCH]);
        float4 a = dp[0], b = dp[1];
        up[0] = a.x; up[1] = a.y; up[2] = a.z; up[3] = a.w;
        up[4] = b.x; up[5] = b.y; up[6] = b.z; up[7] = b.w;
    }
    const float4* src = reinterpret_cast<const float4*>(&g_latT[(size_t)idx * NCH]);
    float4 v0 = src[0], v1 = src[1];
    float v[NCH] = {v0.x, v0.y, v0.z, v0.w, v1.x, v1.y, v1.z, v1.w};

    float* olat = out + 4 * NAGENTS;   // lattice section of output
    #pragma unroll
    for (int c = 0; c < NCH; c++) {
        float val = v[c];
        if (w) val = fmaxf(val + DT * up[c], 0.0f);
        olat[(size_t)c * GG + idx] = val * DECAY;
    }
}

// ---------------------------------------------------------------------------
extern "C" void kernel_launch(void* const* d_in, const int* in_sizes, int n_in,
                              void* d_out, int out_size) {
    const float* agent_pos = (const float*)d_in[0];   // (2, N)
    const float* agent_vel = (const float*)d_in[1];   // (2, N)
    const float* lattice   = (const float*)d_in[2];   // (8, 1024, 1024)
    const float* W1        = (const float*)d_in[3];   // (24, 64)
    const float* b1        = (const float*)d_in[4];   // (64,)
    const float* W2        = (const float*)d_in[5];   // (64, 10)
    const float* b2        = (const float*)d_in[6];   // (10,)
    float* out = (float*)d_out;

    transpose_k<<<(GG + 255) / 256, 256>>>(lattice);
    agent_k<<<NHALF / 256, 256>>>(agent_pos, agent_vel, W1, b1, W2, b2, out);
    latout_k<<<(GG + 255) / 256, 256>>>(out);
}

// round 16
// speedup vs baseline: 1.6564x; 1.0420x over previous
#include <cuda_runtime.h>
#include <math.h>

#define GRIDSZ   1024
#define GG       (GRIDSZ * GRIDSZ)
#define NAGENTS  262144
#define NHALF    (NAGENTS / 2)
#define NCH      8
#define NHID     64
#define DT       0.1f
#define SENS_ANG 0.6f
#define SENS_LEN 3.0f
#define DECAY    0.99f

// Scratch (static __device__ arrays: allocation-free per harness rules)
__device__ float g_latT[GG * NCH];          // lattice transposed (x,y,c), for latout
__device__ float g_latS[GG * NCH];          // y-summed (torus), intermediate
__device__ float g_latB[GG * NCH];          // full 3x3 box sum (torus), for sensing
__device__ float g_dpher[NAGENTS * NCH];    // per-agent d_pheromone
__device__ int   g_winner[GG];              // 0 = none, else agent_id+1 (reset by latout)

// ---------------------------------------------------------------------------
// packed fp32x2 helpers (FFMA2 — only reachable via PTX fma.rn.f32x2)
// ---------------------------------------------------------------------------
typedef unsigned long long u64t;

__device__ __forceinline__ u64t pk2(float lo, float hi) {
    u64t r; asm("mov.b64 %0, {%1, %2};" : "=l"(r) : "f"(lo), "f"(hi)); return r;
}
__device__ __forceinline__ void upk2(u64t v, float& lo, float& hi) {
    asm("mov.b64 {%0, %1}, %2;" : "=f"(lo), "=f"(hi) : "l"(v));
}
__device__ __forceinline__ u64t fma2(u64t a, u64t b, u64t c) {
    u64t d; asm("fma.rn.f32x2 %0, %1, %2, %3;" : "=l"(d) : "l"(a), "l"(b), "l"(c)); return d;
}
__device__ __forceinline__ u64t packbits(float lo, float hi) {
    return ((u64t)__float_as_uint(hi) << 32) | (u64t)__float_as_uint(lo);
}

// fast tanh: 1 - 2/(exp(2a)+1); exact saturation, ~1e-7 rel error
__device__ __forceinline__ float fast_tanh(float a) {
    float t = __expf(2.0f * a);
    return 1.0f - __fdividef(2.0f, t + 1.0f);
}

// ---------------------------------------------------------------------------
// Kernel 1: transpose + y-direction 3-sum (torus). 1 cell/thread.
// Writes g_latT (plain, for latout) and g_latS (y-sum).
// Reads are y-adjacent (same 128B lines across neighboring threads -> L1 hits).
// ---------------------------------------------------------------------------
__global__ void __launch_bounds__(256) prep_k(const float* __restrict__ lat) {
    int idx = blockIdx.x * blockDim.x + threadIdx.x;   // x*GRIDSZ + y
    if (idx >= GG) return;
    int x = idx >> 10;
    int y = idx & (GRIDSZ - 1);
    int ym = (y - 1) & (GRIDSZ - 1);
    int yp = (y + 1) & (GRIDSZ - 1);
    int rb = x << 10;

    float v[NCH], s[NCH];
    #pragma unroll
    for (int c = 0; c < NCH; c++) {
        const float* pl = lat + (size_t)c * GG + rb;
        float vm = pl[ym];
        float v0 = pl[y];
        float vp = pl[yp];
        v[c] = v0;
        s[c] = (vm + v0) + vp;   // dy order: -1, 0, +1
    }
    float4* dt = reinterpret_cast<float4*>(&g_latT[(size_t)idx * NCH]);
    dt[0] = make_float4(v[0], v[1], v[2], v[3]);
    dt[1] = make_float4(v[4], v[5], v[6], v[7]);
    float4* ds = reinterpret_cast<float4*>(&g_latS[(size_t)idx * NCH]);
    ds[0] = make_float4(s[0], s[1], s[2], s[3]);
    ds[1] = make_float4(s[4], s[5], s[6], s[7]);
}

// ---------------------------------------------------------------------------
// Kernel 2: x-direction 3-sum (torus) of g_latS -> g_latB (full 3x3 box).
// x+-1 = +-32KB stride; coalesced 32B/thread; strong L2 reuse between blocks.
// ---------------------------------------------------------------------------
__global__ void __launch_bounds__(256) xsum_k() {
    int idx = blockIdx.x * blockDim.x + threadIdx.x;   // x*GRIDSZ + y
    if (idx >= GG) return;
    int x = idx >> 10;
    int y = idx & (GRIDSZ - 1);
    int xm = (x - 1) & (GRIDSZ - 1);
    int xp = (x + 1) & (GRIDSZ - 1);

    const float4* pm = reinterpret_cast<const float4*>(&g_latS[((size_t)(xm << 10) + y) * NCH]);
    const float4* p0 = reinterpret_cast<const float4*>(&g_latS[((size_t)idx) * NCH]);
    const float4* pp = reinterpret_cast<const float4*>(&g_latS[((size_t)(xp << 10) + y) * NCH]);
    float4 m0 = pm[0], m1 = pm[1];
    float4 a0 = p0[0], a1 = p0[1];
    float4 q0 = pp[0], q1 = pp[1];

    float4 r0, r1;   // dx order: -1, 0, +1
    r0.x = (m0.x + a0.x) + q0.x;  r0.y = (m0.y + a0.y) + q0.y;
    r0.z = (m0.z + a0.z) + q0.z;  r0.w = (m0.w + a0.w) + q0.w;
    r1.x = (m1.x + a1.x) + q1.x;  r1.y = (m1.y + a1.y) + q1.y;
    r1.z = (m1.z + a1.z) + q1.z;  r1.w = (m1.w + a1.w) + q1.w;

    float4* db = reinterpret_cast<float4*>(&g_latB[(size_t)idx * NCH]);
    db[0] = r0;
    db[1] = r1;
}

// ---------------------------------------------------------------------------
// Kernel 3: sense (ONE box-sum cell per sensor) + MLP, TWO agents per thread.
// Gather: 6 LDG.128/agent (was 54) -> L1tex wavefront cost ~9x lower.
// ---------------------------------------------------------------------------
__global__ void __launch_bounds__(256) agent_k(
    const float* __restrict__ pos, const float* __restrict__ vel,
    const float* __restrict__ W1, const float* __restrict__ b1,
    const float* __restrict__ W2, const float* __restrict__ b2,
    float* __restrict__ out)
{
    // sW1p[j*6+q] = { (W1[4q][j], W1[4q+1][j]), (W1[4q+2][j], W1[4q+3][j]) }
    __shared__ ulonglong2 sW1p[NHID * 6];
    // sW2p[j*3+q] = { (W2[j][4q], W2[j][4q+1]), (W2[j][4q+2], W2[j][4q+3]) }, k>=10 -> 0
    __shared__ ulonglong2 sW2p[NHID * 3];
    __shared__ float sb1[NHID];
    __shared__ float sb2[12];

    int tid = threadIdx.x;
    for (int t = tid; t < NHID * 6; t += blockDim.x) {
        int j = t / 6, q = t % 6;
        float e0 = W1[(4 * q + 0) * NHID + j];
        float e1 = W1[(4 * q + 1) * NHID + j];
        float e2 = W1[(4 * q + 2) * NHID + j];
        float e3 = W1[(4 * q + 3) * NHID + j];
        sW1p[t] = make_ulonglong2(packbits(e0, e1), packbits(e2, e3));
    }
    for (int t = tid; t < NHID * 3; t += blockDim.x) {
        int j = t / 3, q = t % 3;
        float e[4];
        #pragma unroll
        for (int u = 0; u < 4; u++) {
            int k = 4 * q + u;
            e[u] = (k < 10) ? W2[j * 10 + k] : 0.0f;
        }
        sW2p[t] = make_ulonglong2(packbits(e[0], e[1]), packbits(e[2], e[3]));
    }
    if (tid < NHID) sb1[tid] = b1[tid];
    if (tid < 12)   sb2[tid] = (tid < 10) ? b2[tid] : 0.0f;
    __syncthreads();

    int t0 = blockIdx.x * blockDim.x + tid;

    float px[2], py[2];
    u64t  f2[2][12];

    // ---- sense both agents: one box-sum cell per sensor ----
    #pragma unroll
    for (int a = 0; a < 2; a++) {
        int i = t0 + a * NHALF;
        float pxa = pos[i], pya = pos[NAGENTS + i];
        float vxa = vel[i], vya = vel[NAGENTS + i];
        px[a] = pxa; py[a] = pya;

        float theta = atan2f(vya, vxa);
        const float offs[3] = {0.0f, SENS_ANG, -SENS_ANG};

        #pragma unroll
        for (int s = 0; s < 3; s++) {
            float sn, cs;
            sincosf(theta + offs[s], &sn, &cs);
            // match JAX mul-then-add rounding (no fma contraction before rint)
            int cx = (int)rintf(__fadd_rn(pxa, __fmul_rn(SENS_LEN, cs)));
            int cy = (int)rintf(__fadd_rn(pya, __fmul_rn(SENS_LEN, sn)));
            int x = cx & (GRIDSZ - 1);
            int y = cy & (GRIDSZ - 1);

            const float4* p = reinterpret_cast<const float4*>(
                &g_latB[((size_t)(x << 10) + y) * NCH]);
            float4 v0 = p[0], v1 = p[1];
            f2[a][s * 4 + 0] = pk2(v0.x, v0.y);
            f2[a][s * 4 + 1] = pk2(v0.z, v0.w);
            f2[a][s * 4 + 2] = pk2(v1.x, v1.y);
            f2[a][s * 4 + 3] = pk2(v1.z, v1.w);
        }
    }

    // ---- MLP: shared weight loads, two independent accumulator chains ----
    u64t o2[2][6];
    #pragma unroll
    for (int kk = 0; kk < 6; kk++) {
        u64t b = pk2(sb2[2 * kk], sb2[2 * kk + 1]);
        o2[0][kk] = b; o2[1][kk] = b;
    }

    #pragma unroll 2
    for (int j = 0; j < NHID; j++) {
        float bj = sb1[j];
        u64t acc0 = pk2(bj, 0.0f);
        u64t acc1 = acc0;
        const ulonglong2* w1r = &sW1p[j * 6];
        #pragma unroll
        for (int q = 0; q < 6; q++) {
            ulonglong2 w = w1r[q];
            acc0 = fma2(f2[0][2 * q],     w.x, acc0);
            acc1 = fma2(f2[1][2 * q],     w.x, acc1);
            acc0 = fma2(f2[0][2 * q + 1], w.y, acc0);
            acc1 = fma2(f2[1][2 * q + 1], w.y, acc1);
        }
        float lo0, hi0, lo1, hi1;
        upk2(acc0, lo0, hi0);
        upk2(acc1, lo1, hi1);
        float h0 = fast_tanh(lo0 + hi0);
        float h1 = fast_tanh(lo1 + hi1);
        u64t hd0 = pk2(h0, h0);
        u64t hd1 = pk2(h1, h1);

        const ulonglong2* w2r = &sW2p[j * 3];
        #pragma unroll
        for (int q = 0; q < 3; q++) {
            ulonglong2 w = w2r[q];
            o2[0][2 * q]     = fma2(hd0, w.x, o2[0][2 * q]);
            o2[1][2 * q]     = fma2(hd1, w.x, o2[1][2 * q]);
            o2[0][2 * q + 1] = fma2(hd0, w.y, o2[0][2 * q + 1]);
            o2[1][2 * q + 1] = fma2(hd1, w.y, o2[1][2 * q + 1]);
        }
    }

    // ---- outputs for both agents ----
    #pragma unroll
    for (int a = 0; a < 2; a++) {
        int i = t0 + a * NHALF;
        float o[12];
        #pragma unroll
        for (int kk = 0; kk < 6; kk++) upk2(o2[a][kk], o[2 * kk], o[2 * kk + 1]);

        // new_pos = (pos + new_vel*DT) mod GRID (python floor-mod, b>0)
        float nx = fmodf(px[a] + o[0] * DT, (float)GRIDSZ); if (nx < 0.0f) nx += (float)GRIDSZ;
        float ny = fmodf(py[a] + o[1] * DT, (float)GRIDSZ); if (ny < 0.0f) ny += (float)GRIDSZ;

        out[0 * NAGENTS + i] = nx;
        out[1 * NAGENTS + i] = ny;
        out[2 * NAGENTS + i] = o[0];
        out[3 * NAGENTS + i] = o[1];

        float4* dp = reinterpret_cast<float4*>(&g_dpher[(size_t)i * NCH]);
        dp[0] = make_float4(o[2], o[3], o[4], o[5]);
        dp[1] = make_float4(o[6], o[7], o[8], o[9]);

        // deterministic duplicate resolution: max agent index wins (== last-
        // wins under sequential scatter). atomicMax is order-independent.
        int pxi = (int)rintf(px[a]);
        int pyi = (int)rintf(py[a]);
        atomicMax(&g_winner[pxi * GRIDSZ + pyi], i + 1);
    }
}

// ---------------------------------------------------------------------------
// Kernel 4: fused decay + scatter + winner reset. Reads lattice values from
// g_latT (L2-resident, 32B-contiguous per thread).
// ---------------------------------------------------------------------------
__global__ void __launch_bounds__(256) latout_k(float* __restrict__ out) {
    int idx = blockIdx.x * blockDim.x + threadIdx.x;   // x*GRIDSZ + y
    if (idx >= GG) return;
    int w = g_winner[idx];
    float up[NCH];
    if (w) {
        g_winner[idx] = 0;   // reset for next graph replay
        const float4* dp = reinterpret_cast<const float4*>(&g_dpher[(size_t)(w - 1) * NCH]);
        float4 a = dp[0], b = dp[1];
        up[0] = a.x; up[1] = a.y; up[2] = a.z; up[3] = a.w;
        up[4] = b.x; up[5] = b.y; up[6] = b.z; up[7] = b.w;
    }
    const float4* src = reinterpret_cast<const float4*>(&g_latT[(size_t)idx * NCH]);
    float4 v0 = src[0], v1 = src[1];
    float v[NCH] = {v0.x, v0.y, v0.z, v0.w, v1.x, v1.y, v1.z, v1.w};

    float* olat = out + 4 * NAGENTS;   // lattice section of output
    #pragma unroll
    for (int c = 0; c < NCH; c++) {
        float val = v[c];
        if (w) val = fmaxf(val + DT * up[c], 0.0f);
        olat[(size_t)c * GG + idx] = val * DECAY;
    }
}

// ---------------------------------------------------------------------------
extern "C" void kernel_launch(void* const* d_in, const int* in_sizes, int n_in,
                              void* d_out, int out_size) {
    const float* agent_pos = (const float*)d_in[0];   // (2, N)
    const float* agent_vel = (const float*)d_in[1];   // (2, N)
    const float* lattice   = (const float*)d_in[2];   // (8, 1024, 1024)
    const float* W1        = (const float*)d_in[3];   // (24, 64)
    const float* b1        = (const float*)d_in[4];   // (64,)
    const float* W2        = (const float*)d_in[5];   // (64, 10)
    const float* b2        = (const float*)d_in[6];   // (10,)
    float* out = (float*)d_out;

    prep_k<<<(GG + 255) / 256, 256>>>(lattice);
    xsum_k<<<(GG + 255) / 256, 256>>>();
    agent_k<<<NHALF / 256, 256>>>(agent_pos, agent_vel, W1, b1, W2, b2, out);
    latout_k<<<(GG + 255) / 256, 256>>>(out);
}